// round 4
// baseline (speedup 1.0000x reference)
#include <cuda_runtime.h>
#include <math.h>

// Problem constants (shapes fixed by setup_inputs)
#define NXV   16384
#define BV    16
#define DH    128
#define DL    64
#define TP    64          // points per block
#define NT    256         // threads per block
#define HALO  3           // k = 3 -> 7 offsets
#define NOFF  7

// Shared memory layout (float offsets)
#define OFF_WN2 0                    // node_w2   128x64
#define OFF_WE2 (OFF_WN2 + DH*DL)    // edge_w2   128x64
#define OFF_WC1 (OFF_WE2 + DH*DL)    // comb_w1   128x128
#define OFF_WC2 (OFF_WC1 + DH*DH)    // comb_w2   128x64
#define OFF_G   (OFF_WC2 + DH*DL)    // activation buffer 64x128
#define OFF_C   (OFF_G   + TP*DH)    // concat buffer     64x128
#define OFF_U   (OFF_C   + TP*DH)    // u0 halo tile (72)
#define OFF_X   (OFF_U   + (TP+2*HALO+2))
#define SMEM_FLOATS (OFF_X + (TP+2*HALO+2))

__device__ __forceinline__ float gelu_exact(float v) {
    return 0.5f * v * (1.0f + erff(v * 0.70710678118654752440f));
}

// C[64p x 64n] = g[64p x 128k] @ W[128k x 64n] + bscale*bias ; dst row stride given.
__device__ __forceinline__ void gemm_64(const float* __restrict__ gbuf,
                                        const float* __restrict__ w,
                                        const float* __restrict__ bias,
                                        float bscale,
                                        float* __restrict__ dst,
                                        int dstStride,
                                        int tid)
{
    const int lg = tid & 15;        // n-group: 4 consecutive cols
    const int pg = tid >> 4;        // p-group: 4 consecutive rows
    float acc[4][4];
    #pragma unroll
    for (int i = 0; i < 4; i++)
        #pragma unroll
        for (int j = 0; j < 4; j++) acc[i][j] = 0.0f;

    const float* g0 = gbuf + (pg * 4) * DH;
    #pragma unroll 4
    for (int k = 0; k < DH; k++) {
        float4 w4 = *(const float4*)(w + k * DL + lg * 4);
        #pragma unroll
        for (int pp = 0; pp < 4; pp++) {
            float gv = g0[pp * DH + k];
            acc[pp][0] = fmaf(gv, w4.x, acc[pp][0]);
            acc[pp][1] = fmaf(gv, w4.y, acc[pp][1]);
            acc[pp][2] = fmaf(gv, w4.z, acc[pp][2]);
            acc[pp][3] = fmaf(gv, w4.w, acc[pp][3]);
        }
    }
    float4 b4 = *(const float4*)(bias + lg * 4);
    #pragma unroll
    for (int pp = 0; pp < 4; pp++) {
        float4 r;
        r.x = fmaf(bscale, b4.x, acc[pp][0]);
        r.y = fmaf(bscale, b4.y, acc[pp][1]);
        r.z = fmaf(bscale, b4.z, acc[pp][2]);
        r.w = fmaf(bscale, b4.w, acc[pp][3]);
        *(float4*)(dst + (pg * 4 + pp) * dstStride + lg * 4) = r;
    }
}

__global__ void __launch_bounds__(NT, 1)
lifting_kernel(const float* __restrict__ u0,     const float* __restrict__ x,
               const float* __restrict__ node_w1, const float* __restrict__ node_b1,
               const float* __restrict__ node_b2,
               const float* __restrict__ edge_w1, const float* __restrict__ edge_b1,
               const float* __restrict__ edge_b2,
               const float* __restrict__ node_w2, const float* __restrict__ edge_w2,
               const float* __restrict__ comb_w1, const float* __restrict__ comb_b1,
               const float* __restrict__ comb_w2, const float* __restrict__ comb_b2,
               float* __restrict__ out)
{
    extern __shared__ float sm[];
    const int tid = threadIdx.x;
    const int blk = blockIdx.x;
    const int b  = blk / (NXV / TP);
    const int i0 = (blk % (NXV / TP)) * TP;
    const float* row_u = u0 + (size_t)b * NXV;
    const float* row_x = x  + (size_t)b * NXV;

    // ---- cooperative weight load into smem (float4) ----
    {
        float4*       d0 = (float4*)(sm + OFF_WN2);
        const float4* s0 = (const float4*)node_w2;
        for (int i = tid; i < DH*DL/4; i += NT) d0[i] = s0[i];
        float4*       d1 = (float4*)(sm + OFF_WE2);
        const float4* s1 = (const float4*)edge_w2;
        for (int i = tid; i < DH*DL/4; i += NT) d1[i] = s1[i];
        float4*       d2 = (float4*)(sm + OFF_WC1);
        const float4* s2 = (const float4*)comb_w1;
        for (int i = tid; i < DH*DH/4; i += NT) d2[i] = s2[i];
        float4*       d3 = (float4*)(sm + OFF_WC2);
        const float4* s3 = (const float4*)comb_w2;
        for (int i = tid; i < DH*DL/4; i += NT) d3[i] = s3[i];
    }
    // ---- u0/x halo tile (clamped indices, matching jnp.clip) ----
    for (int t = tid; t < TP + 2 * HALO; t += NT) {
        int gi = i0 - HALO + t;
        gi = gi < 0 ? 0 : (gi > NXV - 1 ? NXV - 1 : gi);
        sm[OFF_U + t] = row_u[gi];
        sm[OFF_X + t] = row_x[gi];
    }
    __syncthreads();

    const int hh = tid & (DH - 1);  // hidden unit owned by this thread
    const int pg = tid >> 7;        // 0/1: point phase

    // ---- Stage A: node layer-1 + gelu -> g ----
    {
        const float a0 = node_w1[hh];
        const float a1 = node_w1[DH + hh];
        const float bb = node_b1[hh];
        for (int p = pg; p < TP; p += 2) {
            float u  = sm[OFF_U + p + HALO];
            float xx = sm[OFF_X + p + HALO];
            sm[OFF_G + p * DH + hh] = gelu_exact(fmaf(a0, u, fmaf(a1, xx, bb)));
        }
    }
    __syncthreads();

    // ---- GEMM A: c[:, 0:64] = g @ node_w2 + node_b2 (h_self) ----
    gemm_64(sm + OFF_G, sm + OFF_WN2, node_b2, 1.0f, sm + OFF_C, DH, tid);
    __syncthreads();

    // ---- Stage B: edge layer-1, gelu summed over 7 offsets -> g ----
    {
        const float e0 = edge_w1[hh];
        const float e1 = edge_w1[DH + hh];
        const float e2 = edge_w1[2 * DH + hh];
        const float eb = edge_b1[hh];
        for (int p = pg; p < TP; p += 2) {
            float u_i = sm[OFF_U + p + HALO];
            float x_i = sm[OFF_X + p + HALO];
            float s = 0.0f;
            #pragma unroll
            for (int o = 0; o < NOFF; o++) {
                float u_j = sm[OFF_U + p + o];
                float dx  = sm[OFF_X + p + o] - x_i;
                float t = fmaf(e0, u_i, fmaf(e1, u_j, fmaf(e2, dx, eb)));
                s += gelu_exact(t);
            }
            sm[OFF_G + p * DH + hh] = s;
        }
    }
    __syncthreads();

    // ---- GEMM B: c[:, 64:128] = g_edge_sum @ edge_w2 + 7*edge_b2 (agg) ----
    gemm_64(sm + OFF_G, sm + OFF_WE2, edge_b2, (float)NOFF, sm + OFF_C + DL, DH, tid);
    __syncthreads();

    // ---- comb layer-1: g = gelu(c @ comb_w1 + comb_b1) ----
    {
        const int lg  = tid & 15;   // 4-col chunks at lg*4 and 64+lg*4
        const int pgr = tid >> 4;
        float acc[4][8];
        #pragma unroll
        for (int i = 0; i < 4; i++)
            #pragma unroll
            for (int j = 0; j < 8; j++) acc[i][j] = 0.0f;

        const float* c0 = sm + OFF_C + (pgr * 4) * DH;
        #pragma unroll 2
        for (int k = 0; k < DH; k++) {
            float4 wa = *(const float4*)(sm + OFF_WC1 + k * DH + lg * 4);
            float4 wb = *(const float4*)(sm + OFF_WC1 + k * DH + 64 + lg * 4);
            #pragma unroll
            for (int pp = 0; pp < 4; pp++) {
                float cv = c0[pp * DH + k];
                acc[pp][0] = fmaf(cv, wa.x, acc[pp][0]);
                acc[pp][1] = fmaf(cv, wa.y, acc[pp][1]);
                acc[pp][2] = fmaf(cv, wa.z, acc[pp][2]);
                acc[pp][3] = fmaf(cv, wa.w, acc[pp][3]);
                acc[pp][4] = fmaf(cv, wb.x, acc[pp][4]);
                acc[pp][5] = fmaf(cv, wb.y, acc[pp][5]);
                acc[pp][6] = fmaf(cv, wb.z, acc[pp][6]);
                acc[pp][7] = fmaf(cv, wb.w, acc[pp][7]);
            }
        }
        float4 ba = *(const float4*)(comb_b1 + lg * 4);
        float4 bb = *(const float4*)(comb_b1 + 64 + lg * 4);
        __syncthreads();   // c no longer needed; safe before overwriting g
        #pragma unroll
        for (int pp = 0; pp < 4; pp++) {
            float* gd = sm + OFF_G + (pgr * 4 + pp) * DH;
            float4 r0, r1;
            r0.x = gelu_exact(acc[pp][0] + ba.x);
            r0.y = gelu_exact(acc[pp][1] + ba.y);
            r0.z = gelu_exact(acc[pp][2] + ba.z);
            r0.w = gelu_exact(acc[pp][3] + ba.w);
            r1.x = gelu_exact(acc[pp][4] + bb.x);
            r1.y = gelu_exact(acc[pp][5] + bb.y);
            r1.z = gelu_exact(acc[pp][6] + bb.z);
            r1.w = gelu_exact(acc[pp][7] + bb.w);
            *(float4*)(gd + lg * 4)      = r0;
            *(float4*)(gd + 64 + lg * 4) = r1;
        }
    }
    __syncthreads();

    // ---- comb layer-2: out = g @ comb_w2 + comb_b2 -> global ----
    gemm_64(sm + OFF_G, sm + OFF_WC2, comb_b2,
            1.0f, out + ((size_t)b * NXV + i0) * DL, DL, tid);
}

extern "C" void kernel_launch(void* const* d_in, const int* in_sizes, int n_in,
                              void* d_out, int out_size)
{
    const float* u0      = (const float*)d_in[0];
    const float* x       = (const float*)d_in[1];
    const float* node_w1 = (const float*)d_in[2];
    const float* node_b1 = (const float*)d_in[3];
    const float* node_w2 = (const float*)d_in[4];
    const float* node_b2 = (const float*)d_in[5];
    const float* edge_w1 = (const float*)d_in[6];
    const float* edge_b1 = (const float*)d_in[7];
    const float* edge_w2 = (const float*)d_in[8];
    const float* edge_b2 = (const float*)d_in[9];
    const float* comb_w1 = (const float*)d_in[10];
    const float* comb_b1 = (const float*)d_in[11];
    const float* comb_w2 = (const float*)d_in[12];
    const float* comb_b2 = (const float*)d_in[13];
    float* out = (float*)d_out;

    const size_t smem = SMEM_FLOATS * sizeof(float);
    cudaFuncSetAttribute(lifting_kernel,
                         cudaFuncAttributeMaxDynamicSharedMemorySize, (int)smem);

    const int grid = BV * (NXV / TP);   // 4096 blocks
    lifting_kernel<<<grid, NT, smem>>>(u0, x,
                                       node_w1, node_b1, node_b2,
                                       edge_w1, edge_b1, edge_b2,
                                       node_w2, edge_w2,
                                       comb_w1, comb_b1, comb_w2, comb_b2,
                                       out);
}

// round 6
// speedup vs baseline: 1.9916x; 1.9916x over previous
#include <cuda_runtime.h>
#include <cstdint>
#include <math.h>

// ---------------- problem constants ----------------
#define NXV 16384
#define BV  16
#define TP  64            // points per block
#define NT  256
#define NBLK (BV * (NXV / TP))   // 4096
#define KS  132           // padded K stride (floats): bank = lane, conflict-free

// ---------------- smem layout (float offsets) ----------------
#define S_A   0                    // activation / C / G2 buffer 64 x 132
#define S_WN2 (S_A   + TP  * KS)   // node_w2^T 64 x 132
#define S_WE2 (S_WN2 + 64  * KS)   // edge_w2^T 64 x 132
#define S_WC2 (S_WE2 + 64  * KS)   // comb_w2^T 64 x 132
#define S_WC1 (S_WC2 + 64  * KS)   // comb_w1^T 128 x 132
#define S_U   (S_WC1 + 128 * KS)   // u halo (70 -> pad 72)
#define S_X   (S_U + 72)
#define SMEM_FLOATS (S_X + 72)     // 50832 floats = 203328 B

#define WIMG_FLOATS ((64 + 64 + 64 + 128) * KS)   // 42240, contiguous = smem weight region
__device__ float W_IMG[WIMG_FLOATS];

// ---------------- helpers ----------------
__device__ __forceinline__ uint32_t smem_u32(const void* p) {
    uint32_t a;
    asm("{ .reg .u64 t; cvta.to.shared.u64 t, %1; cvt.u32.u64 %0, t; }" : "=r"(a) : "l"(p));
    return a;
}
__device__ __forceinline__ uint32_t f2tf(float f) {   // round-to-nearest tf32 (keeps f32 bit layout)
    uint32_t r; asm("cvt.rna.tf32.f32 %0, %1;" : "=r"(r) : "f"(f)); return r;
}
__device__ __forceinline__ void mma_tf32(float c[4],
                                         uint32_t a0, uint32_t a1, uint32_t a2, uint32_t a3,
                                         uint32_t b0, uint32_t b1) {
    asm volatile("mma.sync.aligned.m16n8k8.row.col.f32.tf32.tf32.f32 "
                 "{%0,%1,%2,%3}, {%4,%5,%6,%7}, {%8,%9}, {%0,%1,%2,%3};"
                 : "+f"(c[0]), "+f"(c[1]), "+f"(c[2]), "+f"(c[3])
                 : "r"(a0), "r"(a1), "r"(a2), "r"(a3), "r"(b0), "r"(b1));
}
#define CP_ASYNC16(dst, src) \
    asm volatile("cp.async.cg.shared.global [%0], [%1], 16;" :: "r"((uint32_t)(dst)), "l"(src) : "memory")
#define CP_COMMIT() asm volatile("cp.async.commit_group;" ::: "memory")
#define CP_WAIT0()  asm volatile("cp.async.wait_group 0;" ::: "memory")

__device__ __forceinline__ float gelu_exact(float v) {
    return 0.5f * v * (1.0f + erff(v * 0.70710678118654752440f));
}

// warp GEMM: D[m16 x n(NT8*8)] += A[m16 x 128] @ W^T[n x 128]^T, K=128, tf32
// A: fp32 activations (cvt at load). W: pre-rounded tf32 in smem.
template <int NTILES>
__device__ __forceinline__ void warp_gemm(const float* __restrict__ A,
                                          const float* __restrict__ W,
                                          float acc[NTILES][4],
                                          int m0, int nb, int lane) {
    const int lr = lane >> 2, lc = lane & 3;
    const float* ar0 = A + (m0 + lr) * KS + lc;
    const float* ar1 = A + (m0 + lr + 8) * KS + lc;
    const float* wr  = W + (nb + lr) * KS + lc;
    #pragma unroll
    for (int k0 = 0; k0 < 128; k0 += 8) {
        uint32_t a0 = f2tf(ar0[k0]);
        uint32_t a1 = f2tf(ar1[k0]);
        uint32_t a2 = f2tf(ar0[k0 + 4]);
        uint32_t a3 = f2tf(ar1[k0 + 4]);
        #pragma unroll
        for (int nt = 0; nt < NTILES; nt++) {
            uint32_t b0 = __float_as_uint(wr[nt * 8 * KS + k0]);
            uint32_t b1 = __float_as_uint(wr[nt * 8 * KS + k0 + 4]);
            mma_tf32(acc[nt], a0, a1, a2, a3, b0, b1);
        }
    }
}

// ---------------- prep: transpose + tf32-round weights into W_IMG ----------------
__global__ void prep_kernel(const float* __restrict__ wn2, const float* __restrict__ we2,
                            const float* __restrict__ wc2, const float* __restrict__ wc1) {
    int stride = gridDim.x * blockDim.x;
    int t0 = blockIdx.x * blockDim.x + threadIdx.x;
    for (int i = t0; i < 128 * 64; i += stride) {      // [K=128, N=64] -> Wt[n][k]
        int k = i >> 6, n = i & 63;
        W_IMG[0 * KS           + n * KS + k] = __uint_as_float(f2tf(wn2[i]));
        W_IMG[64 * KS          + n * KS + k] = __uint_as_float(f2tf(we2[i]));
        W_IMG[128 * KS         + n * KS + k] = __uint_as_float(f2tf(wc2[i]));
    }
    for (int i = t0; i < 128 * 128; i += stride) {     // comb_w1 [128,128]
        int k = i >> 7, n = i & 127;
        W_IMG[192 * KS + n * KS + k] = __uint_as_float(f2tf(wc1[i]));
    }
}

// ---------------- main fused kernel ----------------
__global__ void __launch_bounds__(NT, 1)
lifting_mma_kernel(const float* __restrict__ u0,      const float* __restrict__ x,
                   const float* __restrict__ node_w1, const float* __restrict__ node_b1,
                   const float* __restrict__ node_b2,
                   const float* __restrict__ edge_w1, const float* __restrict__ edge_b1,
                   const float* __restrict__ edge_b2,
                   const float* __restrict__ comb_b1, const float* __restrict__ comb_b2,
                   float* __restrict__ out)
{
    extern __shared__ float sm[];
    const uint32_t smem_base = smem_u32(sm);
    const int tid  = threadIdx.x;
    const int w    = tid >> 5;
    const int lane = tid & 31;
    const int lr   = lane >> 2, lc = lane & 3;
    const int blk  = blockIdx.x;
    const int bb   = blk / (NXV / TP);
    const int i0   = (blk % (NXV / TP)) * TP;
    const float* row_u = u0 + (size_t)bb * NXV;
    const float* row_x = x  + (size_t)bb * NXV;

    // ---- weights: one contiguous async copy (layout identical to smem region) ----
    {
        const uint32_t wdst = smem_base + S_WN2 * 4;
        uint64_t wsrc = __cvta_generic_to_global((const void*)W_IMG);
        #pragma unroll 4
        for (int i = tid; i < WIMG_FLOATS / 4; i += NT)
            CP_ASYNC16(wdst + i * 16, (const void*)(wsrc + (uint64_t)i * 16));
        CP_COMMIT();
    }
    // ---- halo (clamped) ----
    for (int t = tid; t < TP + 6; t += NT) {
        int gi = i0 - 3 + t;
        gi = gi < 0 ? 0 : (gi > NXV - 1 ? NXV - 1 : gi);
        sm[S_U + t] = row_u[gi];
        sm[S_X + t] = row_x[gi];
    }
    __syncthreads();

    const int hh = tid & 127;
    const int ph = tid >> 7;
    const int m0 = (w & 3) * 16;   // warp m-strip
    const int nb = (w >> 2) * 32;  // warp n-half (N=64 GEMMs)

    // ---- Stage 1: edge layer-1, gelu summed over 7 offsets -> A ----
    {
        const float e0 = edge_w1[hh];
        const float e1 = edge_w1[128 + hh];
        const float e2 = edge_w1[256 + hh];
        const float eb = edge_b1[hh];
        for (int p = ph; p < TP; p += 2) {
            float u_i = sm[S_U + p + 3];
            float x_i = sm[S_X + p + 3];
            float s = 0.0f;
            #pragma unroll
            for (int o = 0; o < 7; o++) {
                float t = fmaf(e0, u_i, fmaf(e1, sm[S_U + p + o],
                               fmaf(e2, sm[S_X + p + o] - x_i, eb)));
                s += gelu_exact(t);
            }
            sm[S_A + p * KS + hh] = s;
        }
    }
    CP_WAIT0();
    __syncthreads();

    // ---- MMA edge: accE = G_edge @ We2 (cols 64+nb of C) ----
    float accE[4][4];
    #pragma unroll
    for (int i = 0; i < 4; i++) { accE[i][0]=accE[i][1]=accE[i][2]=accE[i][3]=0.f; }
    warp_gemm<4>(sm + S_A, sm + S_WE2, accE, m0, nb, lane);
    __syncthreads();

    // ---- Stage 2: node layer-1 + gelu -> A ----
    {
        const float a0 = node_w1[hh];
        const float a1 = node_w1[128 + hh];
        const float nbb = node_b1[hh];
        for (int p = ph; p < TP; p += 2) {
            float v = fmaf(a0, sm[S_U + p + 3], fmaf(a1, sm[S_X + p + 3], nbb));
            sm[S_A + p * KS + hh] = gelu_exact(v);
        }
    }
    __syncthreads();

    // ---- MMA node: accN = G_node @ Wn2 (cols nb of C) ----
    float accN[4][4];
    #pragma unroll
    for (int i = 0; i < 4; i++) { accN[i][0]=accN[i][1]=accN[i][2]=accN[i][3]=0.f; }
    warp_gemm<4>(sm + S_A, sm + S_WN2, accN, m0, nb, lane);
    __syncthreads();

    // ---- Stage 3: assemble C = [h_self + b | agg + 7b] into A ----
    #pragma unroll
    for (int nt = 0; nt < 4; nt++) {
        int colx = nb + nt * 8 + lc * 2;             // 0..63 within each half
        float2 bn = *(const float2*)(node_b2 + colx);
        float2 be = *(const float2*)(edge_b2 + colx);
        float* c0 = sm + S_A + (m0 + lr) * KS;
        float* c1 = sm + S_A + (m0 + lr + 8) * KS;
        *(float2*)(c0 + colx)      = make_float2(accN[nt][0] + bn.x, accN[nt][1] + bn.y);
        *(float2*)(c1 + colx)      = make_float2(accN[nt][2] + bn.x, accN[nt][3] + bn.y);
        *(float2*)(c0 + 64 + colx) = make_float2(accE[nt][0] + 7.f * be.x, accE[nt][1] + 7.f * be.y);
        *(float2*)(c1 + 64 + colx) = make_float2(accE[nt][2] + 7.f * be.x, accE[nt][3] + 7.f * be.y);
    }
    __syncthreads();

    // ---- MMA comb1: acc1 = C @ Wc1 (N=128, warp n-half of 64) ----
    float acc1[8][4];
    #pragma unroll
    for (int i = 0; i < 8; i++) { acc1[i][0]=acc1[i][1]=acc1[i][2]=acc1[i][3]=0.f; }
    const int nb1 = (w >> 2) * 64;
    warp_gemm<8>(sm + S_A, sm + S_WC1, acc1, m0, nb1, lane);
    __syncthreads();

    // ---- Stage 4: G2 = gelu(acc1 + comb_b1) -> A ----
    #pragma unroll
    for (int nt = 0; nt < 8; nt++) {
        int col = nb1 + nt * 8 + lc * 2;
        float2 b = *(const float2*)(comb_b1 + col);
        float* g0 = sm + S_A + (m0 + lr) * KS + col;
        float* g1 = sm + S_A + (m0 + lr + 8) * KS + col;
        *(float2*)g0 = make_float2(gelu_exact(acc1[nt][0] + b.x), gelu_exact(acc1[nt][1] + b.y));
        *(float2*)g1 = make_float2(gelu_exact(acc1[nt][2] + b.x), gelu_exact(acc1[nt][3] + b.y));
    }
    __syncthreads();

    // ---- MMA comb2 + epilogue: out = G2 @ Wc2 + comb_b2 ----
    float acc2[4][4];
    #pragma unroll
    for (int i = 0; i < 4; i++) { acc2[i][0]=acc2[i][1]=acc2[i][2]=acc2[i][3]=0.f; }
    warp_gemm<4>(sm + S_A, sm + S_WC2, acc2, m0, nb, lane);

    {
        float* orow0 = out + ((size_t)bb * NXV + i0 + m0 + lr) * 64;
        float* orow1 = orow0 + 8 * 64;
        #pragma unroll
        for (int nt = 0; nt < 4; nt++) {
            int colx = nb + nt * 8 + lc * 2;
            float2 b = *(const float2*)(comb_b2 + colx);
            *(float2*)(orow0 + colx) = make_float2(acc2[nt][0] + b.x, acc2[nt][1] + b.y);
            *(float2*)(orow1 + colx) = make_float2(acc2[nt][2] + b.x, acc2[nt][3] + b.y);
        }
    }
}

extern "C" void kernel_launch(void* const* d_in, const int* in_sizes, int n_in,
                              void* d_out, int out_size)
{
    const float* u0      = (const float*)d_in[0];
    const float* x       = (const float*)d_in[1];
    const float* node_w1 = (const float*)d_in[2];
    const float* node_b1 = (const float*)d_in[3];
    const float* node_w2 = (const float*)d_in[4];
    const float* node_b2 = (const float*)d_in[5];
    const float* edge_w1 = (const float*)d_in[6];
    const float* edge_b1 = (const float*)d_in[7];
    const float* edge_w2 = (const float*)d_in[8];
    const float* edge_b2 = (const float*)d_in[9];
    const float* comb_w1 = (const float*)d_in[10];
    const float* comb_b1 = (const float*)d_in[11];
    const float* comb_w2 = (const float*)d_in[12];
    const float* comb_b2 = (const float*)d_in[13];
    float* out = (float*)d_out;

    prep_kernel<<<48, 256>>>(node_w2, edge_w2, comb_w2, comb_w1);

    const size_t smem = SMEM_FLOATS * sizeof(float);
    cudaFuncSetAttribute(lifting_mma_kernel,
                         cudaFuncAttributeMaxDynamicSharedMemorySize, (int)smem);
    lifting_mma_kernel<<<NBLK, NT, smem>>>(u0, x,
                                           node_w1, node_b1, node_b2,
                                           edge_w1, edge_b1, edge_b2,
                                           comb_b1, comb_b2,
                                           out);
}

// round 7
// speedup vs baseline: 2.3797x; 1.1948x over previous
#include <cuda_runtime.h>
#include <cstdint>
#include <math.h>

// ---------------- problem constants ----------------
#define NXV 16384
#define BV  16
#define TP  128           // points per block
#define NT  512           // threads per block (16 warps)
#define NBLK (BV * (NXV / TP))   // 2048

// ---------------- swizzled tile addressing ----------------
// element (row, k) of a [rows x 128] f32 tile; conflict-free for mma fragments
__device__ __forceinline__ int SW(int row, int k) {
    return row * 128 + (k ^ ((row & 7) << 2));
}

// ---------------- smem layout (float offsets) ----------------
#define S_A   0                  // activation / C / G2 buffer 128 x 128
#define S_WN2 16384              // node_w2^T  64 x 128
#define S_WE2 24576              // edge_w2^T  64 x 128
#define S_WC2 32768              // comb_w2^T  64 x 128
#define S_WC1 40960              // comb_w1^T 128 x 128
#define S_U   57344              // u halo (134 -> 136)
#define S_X   (S_U + 136)
#define SMEM_FLOATS (S_X + 136)  // 57616 floats = 230464 B (< 227KB limit)

#define WIMG_FLOATS 40960        // contiguous image of smem weight region
__device__ float W_IMG[WIMG_FLOATS];

// ---------------- helpers ----------------
__device__ __forceinline__ uint32_t smem_u32(const void* p) {
    uint32_t a;
    asm("{ .reg .u64 t; cvta.to.shared.u64 t, %1; cvt.u32.u64 %0, t; }" : "=r"(a) : "l"(p));
    return a;
}
__device__ __forceinline__ uint32_t f2tf(float f) {   // tf32 round-to-nearest, f32 bit layout
    uint32_t r; asm("cvt.rna.tf32.f32 %0, %1;" : "=r"(r) : "f"(f)); return r;
}
__device__ __forceinline__ float f2tff(float f) { return __uint_as_float(f2tf(f)); }

__device__ __forceinline__ void mma_tf32(float c[4],
                                         uint32_t a0, uint32_t a1, uint32_t a2, uint32_t a3,
                                         uint32_t b0, uint32_t b1) {
    asm volatile("mma.sync.aligned.m16n8k8.row.col.f32.tf32.tf32.f32 "
                 "{%0,%1,%2,%3}, {%4,%5,%6,%7}, {%8,%9}, {%0,%1,%2,%3};"
                 : "+f"(c[0]), "+f"(c[1]), "+f"(c[2]), "+f"(c[3])
                 : "r"(a0), "r"(a1), "r"(a2), "r"(a3), "r"(b0), "r"(b1));
}
#define CP_ASYNC16(dst, src) \
    asm volatile("cp.async.cg.shared.global [%0], [%1], 16;" :: "r"((uint32_t)(dst)), "l"(src) : "memory")
#define CP_COMMIT() asm volatile("cp.async.commit_group;" ::: "memory")
#define CP_WAIT0()  asm volatile("cp.async.wait_group 0;" ::: "memory")

// Abramowitz-Stegun 7.1.26 erf (|abs err| <= 1.5e-7), branch-free gelu.
__device__ __forceinline__ float gelu_fast(float v) {
    float ax = fabsf(v) * 0.70710678118654752440f;      // |v|/sqrt(2)
    float t  = __fdividef(1.0f, fmaf(0.3275911f, ax, 1.0f));
    float y  = fmaf(t, 1.061405429f, -1.453152027f);
    y = fmaf(y, t, 1.421413741f);
    y = fmaf(y, t, -0.284496736f);
    y = fmaf(y, t, 0.254829592f);
    y = y * t;
    float e    = __expf(-ax * ax);
    float erfv = fmaf(-y, e, 1.0f);                      // erf(|v|/sqrt(2))
    float phi  = fmaf(copysignf(erfv, v), 0.5f, 0.5f);   // 0.5*(1+erf(v/sqrt2))
    return v * phi;
}

// warp GEMM: D[m16 x NTILES*8] += A[m16 x 128] @ W^T, K=128, tf32.
// A and W hold pre-tf32-rounded f32 bit patterns in swizzled layout.
template <int NTILES>
__device__ __forceinline__ void warp_gemm(const float* __restrict__ A,
                                          const float* __restrict__ W,
                                          float acc[NTILES][4],
                                          int m0, int nbase, int lr, int lc) {
    const float* ar0 = A + (m0 + lr) * 128;
    const float* ar1 = ar0 + 8 * 128;
    const float* wr  = W + (nbase + lr) * 128;
    const int sl = lr << 2;
    #pragma unroll
    for (int k0 = 0; k0 < 128; k0 += 8) {
        int i0 = (k0 + lc) ^ sl;
        int i4 = i0 ^ 4;
        uint32_t a0 = __float_as_uint(ar0[i0]);
        uint32_t a1 = __float_as_uint(ar1[i0]);
        uint32_t a2 = __float_as_uint(ar0[i4]);
        uint32_t a3 = __float_as_uint(ar1[i4]);
        #pragma unroll
        for (int nt = 0; nt < NTILES; nt++) {
            uint32_t b0 = __float_as_uint(wr[nt * 8 * 128 + i0]);
            uint32_t b1 = __float_as_uint(wr[nt * 8 * 128 + i4]);
            mma_tf32(acc[nt], a0, a1, a2, a3, b0, b1);
        }
    }
}

// ---------------- prep: transpose + tf32-round + swizzle weights ----------------
__global__ void prep_kernel(const float* __restrict__ wn2, const float* __restrict__ we2,
                            const float* __restrict__ wc2, const float* __restrict__ wc1) {
    int stride = gridDim.x * blockDim.x;
    int t0 = blockIdx.x * blockDim.x + threadIdx.x;
    for (int i = t0; i < 128 * 64; i += stride) {        // [K=128, N=64] -> Wt[n][k]
        int k = i >> 6, n = i & 63;
        W_IMG[0     + SW(n, k)] = f2tff(wn2[i]);
        W_IMG[8192  + SW(n, k)] = f2tff(we2[i]);
        W_IMG[16384 + SW(n, k)] = f2tff(wc2[i]);
    }
    for (int i = t0; i < 128 * 128; i += stride) {       // comb_w1 [128,128]
        int k = i >> 7, n = i & 127;
        W_IMG[24576 + SW(n, k)] = f2tff(wc1[i]);
    }
}

// ---------------- main fused kernel ----------------
__global__ void __launch_bounds__(NT, 1)
lifting_mma_kernel(const float* __restrict__ u0,      const float* __restrict__ x,
                   const float* __restrict__ node_w1, const float* __restrict__ node_b1,
                   const float* __restrict__ node_b2,
                   const float* __restrict__ edge_w1, const float* __restrict__ edge_b1,
                   const float* __restrict__ edge_b2,
                   const float* __restrict__ comb_b1, const float* __restrict__ comb_b2,
                   float* __restrict__ out)
{
    extern __shared__ float sm[];
    const uint32_t smem_base = smem_u32(sm);
    const int tid  = threadIdx.x;
    const int w    = tid >> 5;
    const int lane = tid & 31;
    const int lr   = lane >> 2, lc = lane & 3;
    const int blk  = blockIdx.x;
    const int bb   = blk / (NXV / TP);
    const int i0   = (blk % (NXV / TP)) * TP;
    const float* row_u = u0 + (size_t)bb * NXV;
    const float* row_x = x  + (size_t)bb * NXV;

    // ---- weights: contiguous async copy of the pre-swizzled image ----
    {
        const uint32_t wdst = smem_base + S_WN2 * 4;
        uint64_t wsrc = __cvta_generic_to_global((const void*)W_IMG);
        #pragma unroll 4
        for (int i = tid; i < WIMG_FLOATS / 4; i += NT)
            CP_ASYNC16(wdst + i * 16, (const void*)(wsrc + (uint64_t)i * 16));
        CP_COMMIT();
    }
    // ---- halo (clamped) ----
    for (int t = tid; t < TP + 6; t += NT) {
        int gi = i0 - 3 + t;
        gi = gi < 0 ? 0 : (gi > NXV - 1 ? NXV - 1 : gi);
        sm[S_U + t] = row_u[gi];
        sm[S_X + t] = row_x[gi];
    }
    __syncthreads();

    const int hh = tid & 127;       // hidden unit
    const int ph = tid >> 7;        // point phase 0..3
    const int m0 = (w & 7) * 16;    // warp m-strip (8 strips)
    const int nh = w >> 3;          // warp n-half
    const int nb  = nh * 32;        // N=64 GEMM half
    const int nb1 = nh * 64;        // N=128 GEMM half

    // ---- Stage 1: edge layer-1, gelu summed over 7 offsets -> A ----
    {
        const float e0 = edge_w1[hh];
        const float e1 = edge_w1[128 + hh];
        const float e2 = edge_w1[256 + hh];
        const float eb = edge_b1[hh];
        for (int p = ph; p < TP; p += 4) {
            float u_i = sm[S_U + p + 3];
            float x_i = sm[S_X + p + 3];
            float s = 0.0f;
            #pragma unroll
            for (int o = 0; o < 7; o++) {
                float t = fmaf(e0, u_i, fmaf(e1, sm[S_U + p + o],
                               fmaf(e2, sm[S_X + p + o] - x_i, eb)));
                s += gelu_fast(t);
            }
            sm[S_A + SW(p, hh)] = f2tff(s);
        }
    }
    CP_WAIT0();
    __syncthreads();

    // ---- MMA edge: accE = G_edge @ We2 ----
    float accE[4][4];
    #pragma unroll
    for (int i = 0; i < 4; i++) { accE[i][0]=accE[i][1]=accE[i][2]=accE[i][3]=0.f; }
    warp_gemm<4>(sm + S_A, sm + S_WE2, accE, m0, nb, lr, lc);
    __syncthreads();

    // ---- Stage 2: node layer-1 + gelu -> A ----
    {
        const float a0 = node_w1[hh];
        const float a1 = node_w1[128 + hh];
        const float nbb = node_b1[hh];
        for (int p = ph; p < TP; p += 4) {
            float v = fmaf(a0, sm[S_U + p + 3], fmaf(a1, sm[S_X + p + 3], nbb));
            sm[S_A + SW(p, hh)] = f2tff(gelu_fast(v));
        }
    }
    __syncthreads();

    // ---- MMA node: accN = G_node @ Wn2 ----
    float accN[4][4];
    #pragma unroll
    for (int i = 0; i < 4; i++) { accN[i][0]=accN[i][1]=accN[i][2]=accN[i][3]=0.f; }
    warp_gemm<4>(sm + S_A, sm + S_WN2, accN, m0, nb, lr, lc);
    __syncthreads();

    // ---- Stage 3: assemble C = [h_self + b | agg + 7b] into A (pre-rounded) ----
    {
        float* c0 = sm + S_A + (m0 + lr) * 128;
        float* c1 = c0 + 8 * 128;
        const int sl = lr << 2;
        #pragma unroll
        for (int nt = 0; nt < 4; nt++) {
            int colx = nb + nt * 8 + lc * 2;
            int swn = colx ^ sl;              // node cols 0..63
            int swe = (64 + colx) ^ sl;       // edge cols 64..127
            float2 bn = *(const float2*)(node_b2 + colx);
            float2 be = *(const float2*)(edge_b2 + colx);
            *(float2*)(c0 + swn) = make_float2(f2tff(accN[nt][0] + bn.x), f2tff(accN[nt][1] + bn.y));
            *(float2*)(c1 + swn) = make_float2(f2tff(accN[nt][2] + bn.x), f2tff(accN[nt][3] + bn.y));
            *(float2*)(c0 + swe) = make_float2(f2tff(accE[nt][0] + 7.f * be.x), f2tff(accE[nt][1] + 7.f * be.y));
            *(float2*)(c1 + swe) = make_float2(f2tff(accE[nt][2] + 7.f * be.x), f2tff(accE[nt][3] + 7.f * be.y));
        }
    }
    __syncthreads();

    // ---- MMA comb1: acc1 = C @ Wc1 (N=128, warp n-half of 64) ----
    float acc1[8][4];
    #pragma unroll
    for (int i = 0; i < 8; i++) { acc1[i][0]=acc1[i][1]=acc1[i][2]=acc1[i][3]=0.f; }
    warp_gemm<8>(sm + S_A, sm + S_WC1, acc1, m0, nb1, lr, lc);
    __syncthreads();

    // ---- Stage 4: G2 = gelu(acc1 + comb_b1) -> A (pre-rounded) ----
    {
        float* g0 = sm + S_A + (m0 + lr) * 128;
        float* g1 = g0 + 8 * 128;
        const int sl = lr << 2;
        #pragma unroll
        for (int nt = 0; nt < 8; nt++) {
            int col = nb1 + nt * 8 + lc * 2;
            int sw  = col ^ sl;
            float2 b = *(const float2*)(comb_b1 + col);
            *(float2*)(g0 + sw) = make_float2(f2tff(gelu_fast(acc1[nt][0] + b.x)),
                                              f2tff(gelu_fast(acc1[nt][1] + b.y)));
            *(float2*)(g1 + sw) = make_float2(f2tff(gelu_fast(acc1[nt][2] + b.x)),
                                              f2tff(gelu_fast(acc1[nt][3] + b.y)));
        }
    }
    __syncthreads();

    // ---- MMA comb2 + epilogue: out = G2 @ Wc2 + comb_b2 ----
    float acc2[4][4];
    #pragma unroll
    for (int i = 0; i < 4; i++) { acc2[i][0]=acc2[i][1]=acc2[i][2]=acc2[i][3]=0.f; }
    warp_gemm<4>(sm + S_A, sm + S_WC2, acc2, m0, nb, lr, lc);

    {
        float* orow0 = out + ((size_t)bb * NXV + i0 + m0 + lr) * 64;
        float* orow1 = orow0 + 8 * 64;
        #pragma unroll
        for (int nt = 0; nt < 4; nt++) {
            int colx = nb + nt * 8 + lc * 2;
            float2 b = *(const float2*)(comb_b2 + colx);
            *(float2*)(orow0 + colx) = make_float2(acc2[nt][0] + b.x, acc2[nt][1] + b.y);
            *(float2*)(orow1 + colx) = make_float2(acc2[nt][2] + b.x, acc2[nt][3] + b.y);
        }
    }
}

extern "C" void kernel_launch(void* const* d_in, const int* in_sizes, int n_in,
                              void* d_out, int out_size)
{
    const float* u0      = (const float*)d_in[0];
    const float* x       = (const float*)d_in[1];
    const float* node_w1 = (const float*)d_in[2];
    const float* node_b1 = (const float*)d_in[3];
    const float* node_w2 = (const float*)d_in[4];
    const float* node_b2 = (const float*)d_in[5];
    const float* edge_w1 = (const float*)d_in[6];
    const float* edge_b1 = (const float*)d_in[7];
    const float* edge_w2 = (const float*)d_in[8];
    const float* edge_b2 = (const float*)d_in[9];
    const float* comb_w1 = (const float*)d_in[10];
    const float* comb_b1 = (const float*)d_in[11];
    const float* comb_w2 = (const float*)d_in[12];
    const float* comb_b2 = (const float*)d_in[13];
    float* out = (float*)d_out;

    prep_kernel<<<48, 256>>>(node_w2, edge_w2, comb_w2, comb_w1);

    const size_t smem = SMEM_FLOATS * sizeof(float);
    cudaFuncSetAttribute(lifting_mma_kernel,
                         cudaFuncAttributeMaxDynamicSharedMemorySize, (int)smem);
    lifting_mma_kernel<<<NBLK, NT, smem>>>(u0, x,
                                           node_w1, node_b1, node_b2,
                                           edge_w1, edge_b1, edge_b2,
                                           comb_b1, comb_b2,
                                           out);
}

// round 9
// speedup vs baseline: 2.7544x; 1.1575x over previous
#include <cuda_runtime.h>
#include <cstdint>
#include <math.h>

// ---------------- problem constants ----------------
#define NXV 16384
#define BV  16
#define TP  128           // points per block
#define NT  512           // threads per block (16 warps)
#define NBLK (BV * (NXV / TP))   // 2048

// ---------------- swizzled tile addressing ----------------
__device__ __forceinline__ int SW(int row, int k) {
    return row * 128 + (k ^ ((row & 7) << 2));
}

// ---------------- smem layout (float offsets) ----------------
#define S_A   0                  // activation / C / G2 buffer 128 x 128
#define S_WN2 16384              // node_w2^T  64 x 128
#define S_WE2 24576              // edge_w2^T  64 x 128
#define S_WC2 32768              // comb_w2^T  64 x 128
#define S_WC1 40960              // comb_w1^T 128 x 128
#define S_U   57344              // u halo (134 -> 136)
#define S_X   (S_U + 136)
#define SMEM_FLOATS (S_X + 136)  // 57616 floats = 230464 B

#define WIMG_FLOATS 40960
__device__ float W_IMG[WIMG_FLOATS];

typedef unsigned long long u64;

// ---------------- packed f32x2 ops (PTX 8.6, sm_100+ base ISA) ----------------
__device__ __forceinline__ u64 pk2(float lo, float hi) {
    u64 r; asm("mov.b64 %0,{%1,%2};" : "=l"(r) : "f"(lo), "f"(hi)); return r;
}
__device__ __forceinline__ void upk2(float& lo, float& hi, u64 v) {
    asm("mov.b64 {%0,%1},%2;" : "=f"(lo), "=f"(hi) : "l"(v));
}
__device__ __forceinline__ u64 fma2_(u64 a, u64 b, u64 c) {
    u64 d; asm("fma.rn.f32x2 %0,%1,%2,%3;" : "=l"(d) : "l"(a), "l"(b), "l"(c)); return d;
}
__device__ __forceinline__ u64 mul2_(u64 a, u64 b) {
    u64 d; asm("mul.rn.f32x2 %0,%1,%2;" : "=l"(d) : "l"(a), "l"(b)); return d;
}
__device__ __forceinline__ u64 add2_(u64 a, u64 b) {
    u64 d; asm("add.rn.f32x2 %0,%1,%2;" : "=l"(d) : "l"(a), "l"(b)); return d;
}
__device__ __forceinline__ u64 rcp2_(u64 a) {
    float lo, hi; upk2(lo, hi, a);
    float rl, rh;
    asm("rcp.approx.f32 %0,%1;" : "=f"(rl) : "f"(lo));
    asm("rcp.approx.f32 %0,%1;" : "=f"(rh) : "f"(hi));
    return pk2(rl, rh);
}

// bit-literal pairs
#define P_HALF 0x3F0000003F000000ULL   // (0.5f, 0.5f)
#define P_ONE  0x3F8000003F800000ULL   // (1.0f, 1.0f)
#define P_CINV 0x3F3504F33F3504F3ULL   // (0.70710678f, 0.70710678f)
#define P_NCV  0xBF3504F3BF3504F3ULL   // (-0.70710678f, ...)
#define P_SEVEN 0x40E0000040E00000ULL  // (7.0f, 7.0f)
#define P_ABSM 0x7FFFFFFF7FFFFFFFULL

// A&S 7.1.28 coefficient pairs (runtime-packed once per kernel, CSE-hoisted)
struct GConst { u64 A1, A2, A3, A4, A5, A6; };
__device__ __forceinline__ GConst make_gc() {
    GConst g;
    g.A1 = pk2(0.0705230784f, 0.0705230784f);
    g.A2 = pk2(0.0422820123f, 0.0422820123f);
    g.A3 = pk2(0.0092705272f, 0.0092705272f);
    g.A4 = pk2(0.0001520143f, 0.0001520143f);
    g.A5 = pk2(0.0002765672f, 0.0002765672f);
    g.A6 = pk2(0.0000430638f, 0.0000430638f);
    return g;
}

// core: gelu(t) = 0.5*t + ax*h, ax = |t|/sqrt2 signed-folded, h = 0.7071*(1-r^16)
__device__ __forceinline__ u64 gelu2_h(u64 t2, u64& ax_out, const GConst& g) {
    u64 ax = mul2_(t2, P_CINV) & P_ABSM;          // |t|/sqrt2
    u64 d = fma2_(ax, g.A6, g.A5);
    d = fma2_(d, ax, g.A4);
    d = fma2_(d, ax, g.A3);
    d = fma2_(d, ax, g.A2);
    d = fma2_(d, ax, g.A1);
    d = fma2_(d, ax, P_ONE);
    u64 r = rcp2_(d);
    r = mul2_(r, r); r = mul2_(r, r); r = mul2_(r, r); r = mul2_(r, r);   // r^16
    ax_out = ax;
    return fma2_(r, P_NCV, P_CINV);               // h = 0.7071*(1-r16)
}
__device__ __forceinline__ u64 gelu2_acc(u64 t2, u64 s2, const GConst& g) {
    u64 ax, h;
    h = gelu2_h(t2, ax, g);
    s2 = fma2_(t2, P_HALF, s2);
    return fma2_(ax, h, s2);
}
__device__ __forceinline__ u64 gelu2(u64 t2, const GConst& g) {
    u64 ax, h;
    h = gelu2_h(t2, ax, g);
    return fma2_(t2, P_HALF, mul2_(ax, h));
}

// ---------------- misc helpers ----------------
__device__ __forceinline__ uint32_t smem_u32(const void* p) {
    uint32_t a;
    asm("{ .reg .u64 t; cvta.to.shared.u64 t, %1; cvt.u32.u64 %0, t; }" : "=r"(a) : "l"(p));
    return a;
}
__device__ __forceinline__ uint32_t f2tf(float f) {
    uint32_t r; asm("cvt.rna.tf32.f32 %0, %1;" : "=r"(r) : "f"(f)); return r;
}
__device__ __forceinline__ float f2tff(float f) { return __uint_as_float(f2tf(f)); }

__device__ __forceinline__ void mma_tf32(float c[4],
                                         uint32_t a0, uint32_t a1, uint32_t a2, uint32_t a3,
                                         uint32_t b0, uint32_t b1) {
    asm volatile("mma.sync.aligned.m16n8k8.row.col.f32.tf32.tf32.f32 "
                 "{%0,%1,%2,%3}, {%4,%5,%6,%7}, {%8,%9}, {%0,%1,%2,%3};"
                 : "+f"(c[0]), "+f"(c[1]), "+f"(c[2]), "+f"(c[3])
                 : "r"(a0), "r"(a1), "r"(a2), "r"(a3), "r"(b0), "r"(b1));
}
#define CP_ASYNC16(dst, src) \
    asm volatile("cp.async.cg.shared.global [%0], [%1], 16;" :: "r"((uint32_t)(dst)), "l"(src) : "memory")
#define CP_COMMIT() asm volatile("cp.async.commit_group;" ::: "memory")
#define CP_WAIT0()  asm volatile("cp.async.wait_group 0;" ::: "memory")

// warp GEMM: D[m16 x NTILES*8] += A[m16 x 128] @ W^T, K=128, tf32 (layout verified in R6)
template <int NTILES>
__device__ __forceinline__ void warp_gemm(const float* __restrict__ A,
                                          const float* __restrict__ W,
                                          float acc[NTILES][4],
                                          int m0, int nbase, int lr, int lc) {
    const float* ar0 = A + (m0 + lr) * 128;
    const float* ar1 = ar0 + 8 * 128;
    const float* wr  = W + (nbase + lr) * 128;
    const int sl = lr << 2;
    #pragma unroll
    for (int k0 = 0; k0 < 128; k0 += 8) {
        int i0 = (k0 + lc) ^ sl;
        int i4 = i0 ^ 4;
        uint32_t a0 = __float_as_uint(ar0[i0]);
        uint32_t a1 = __float_as_uint(ar1[i0]);
        uint32_t a2 = __float_as_uint(ar0[i4]);
        uint32_t a3 = __float_as_uint(ar1[i4]);
        #pragma unroll
        for (int nt = 0; nt < NTILES; nt++) {
            uint32_t b0 = __float_as_uint(wr[nt * 8 * 128 + i0]);
            uint32_t b1 = __float_as_uint(wr[nt * 8 * 128 + i4]);
            mma_tf32(acc[nt], a0, a1, a2, a3, b0, b1);
        }
    }
}

// ---------------- prep: transpose + tf32-round + swizzle weights ----------------
__global__ void prep_kernel(const float* __restrict__ wn2, const float* __restrict__ we2,
                            const float* __restrict__ wc2, const float* __restrict__ wc1) {
    int stride = gridDim.x * blockDim.x;
    int t0 = blockIdx.x * blockDim.x + threadIdx.x;
    for (int i = t0; i < 128 * 64; i += stride) {
        int k = i >> 6, n = i & 63;
        W_IMG[0     + SW(n, k)] = f2tff(wn2[i]);
        W_IMG[8192  + SW(n, k)] = f2tff(we2[i]);
        W_IMG[16384 + SW(n, k)] = f2tff(wc2[i]);
    }
    for (int i = t0; i < 128 * 128; i += stride) {
        int k = i >> 7, n = i & 127;
        W_IMG[24576 + SW(n, k)] = f2tff(wc1[i]);
    }
}

// ---------------- main fused kernel ----------------
__global__ void __launch_bounds__(NT, 1)
lifting_mma_kernel(const float* __restrict__ u0,      const float* __restrict__ x,
                   const float* __restrict__ node_w1, const float* __restrict__ node_b1,
                   const float* __restrict__ node_b2,
                   const float* __restrict__ edge_w1, const float* __restrict__ edge_b1,
                   const float* __restrict__ edge_b2,
                   const float* __restrict__ comb_b1, const float* __restrict__ comb_b2,
                   float* __restrict__ out)
{
    extern __shared__ float sm[];
    const uint32_t smem_base = smem_u32(sm);
    const int tid  = threadIdx.x;
    const int w    = tid >> 5;
    const int lane = tid & 31;
    const int lr   = lane >> 2, lc = lane & 3;
    const int blk  = blockIdx.x;
    const int bb   = blk / (NXV / TP);
    const int i0   = (blk % (NXV / TP)) * TP;
    const float* row_u = u0 + (size_t)bb * NXV;
    const float* row_x = x  + (size_t)bb * NXV;

    // ---- weights: contiguous async copy of the pre-swizzled image ----
    {
        const uint32_t wdst = smem_base + S_WN2 * 4;
        uint64_t wsrc = __cvta_generic_to_global((const void*)W_IMG);
        #pragma unroll 4
        for (int i = tid; i < WIMG_FLOATS / 4; i += NT)
            CP_ASYNC16(wdst + i * 16, (const void*)(wsrc + (uint64_t)i * 16));
        CP_COMMIT();
    }
    // ---- halo (clamped) ----
    for (int t = tid; t < TP + 6; t += NT) {
        int gi = i0 - 3 + t;
        gi = gi < 0 ? 0 : (gi > NXV - 1 ? NXV - 1 : gi);
        sm[S_U + t] = row_u[gi];
        sm[S_X + t] = row_x[gi];
    }
    __syncthreads();

    const GConst gc = make_gc();

    const int hh = tid & 127;       // hidden unit
    const int ph = tid >> 7;        // phase 0..3
    const int m0 = (w & 7) * 16;    // warp m-strip
    const int nh = w >> 3;          // warp n-half
    const int nb  = nh * 32;
    const int nb1 = nh * 64;

    // ---- Stage 1: edge layer-1 (7-offset gelu sum), packed pairs -> A ----
    {
        const float e0 = edge_w1[hh];
        const float e1 = edge_w1[128 + hh];
        const float e2 = edge_w1[256 + hh];
        const float eb = edge_b1[hh];
        const float e01 = e0 + e1;
        #pragma unroll 1
        for (int i = 0; i < 16; i++) {
            const int p0 = 2 * ph + 8 * i;      // pair (p0, p0+1)
            float zz[8];
            #pragma unroll
            for (int j = 0; j < 8; j += 2) {    // z_j = e1*u + e2*x, halo idx p0+j
                float2 uu = *(const float2*)(sm + S_U + p0 + j);
                float2 xx = *(const float2*)(sm + S_X + p0 + j);
                zz[j]     = fmaf(e1, uu.x, e2 * xx.x);
                zz[j + 1] = fmaf(e1, uu.y, e2 * xx.y);
            }
            float ba = fmaf(e01, sm[S_U + p0 + 3], eb) - zz[3];
            float bc = fmaf(e01, sm[S_U + p0 + 4], eb) - zz[4];
            u64 base2 = pk2(ba, bc);
            u64 sA = 0ull, sB = 0ull;           // two accumulators for ILP
            #pragma unroll
            for (int o = 0; o < 7; o++) {
                u64 t2 = add2_(base2, pk2(zz[o], zz[o + 1]));
                if (o & 1) sB = gelu2_acc(t2, sB, gc);
                else       sA = gelu2_acc(t2, sA, gc);
            }
            u64 s2 = add2_(sA, sB);
            float slo, shi; upk2(slo, shi, s2);
            sm[S_A + SW(p0, hh)]     = f2tff(slo);
            sm[S_A + SW(p0 + 1, hh)] = f2tff(shi);
        }
    }
    CP_WAIT0();
    __syncthreads();

    // ---- MMA edge ----
    float accE[4][4];
    #pragma unroll
    for (int i = 0; i < 4; i++) { accE[i][0]=accE[i][1]=accE[i][2]=accE[i][3]=0.f; }
    warp_gemm<4>(sm + S_A, sm + S_WE2, accE, m0, nb, lr, lc);
    __syncthreads();

    // ---- Stage 2: node layer-1 + gelu (packed) -> A ----
    {
        const float a0 = node_w1[hh];
        const float a1 = node_w1[128 + hh];
        const float nbb = node_b1[hh];
        #pragma unroll 1
        for (int i = 0; i < 16; i++) {
            const int p0 = 2 * ph + 8 * i;
            float va = fmaf(a0, sm[S_U + p0 + 3], fmaf(a1, sm[S_X + p0 + 3], nbb));
            float vb = fmaf(a0, sm[S_U + p0 + 4], fmaf(a1, sm[S_X + p0 + 4], nbb));
            u64 g2 = gelu2(pk2(va, vb), gc);
            float glo, ghi; upk2(glo, ghi, g2);
            sm[S_A + SW(p0, hh)]     = f2tff(glo);
            sm[S_A + SW(p0 + 1, hh)] = f2tff(ghi);
        }
    }
    __syncthreads();

    // ---- MMA node ----
    float accN[4][4];
    #pragma unroll
    for (int i = 0; i < 4; i++) { accN[i][0]=accN[i][1]=accN[i][2]=accN[i][3]=0.f; }
    warp_gemm<4>(sm + S_A, sm + S_WN2, accN, m0, nb, lr, lc);
    __syncthreads();

    // ---- Stage 3: assemble C = [h_self + b | agg + 7b] (packed adds) ----
    {
        float* c0 = sm + S_A + (m0 + lr) * 128;
        float* c1 = c0 + 8 * 128;
        const int sl = lr << 2;
        #pragma unroll
        for (int nt = 0; nt < 4; nt++) {
            int colx = nb + nt * 8 + lc * 2;
            int swn = colx ^ sl;
            int swe = (64 + colx) ^ sl;
            float2 bnf = *(const float2*)(node_b2 + colx);
            float2 bef = *(const float2*)(edge_b2 + colx);
            u64 bn2 = pk2(bnf.x, bnf.y);
            u64 be2 = pk2(bef.x, bef.y);
            u64 n01 = add2_(pk2(accN[nt][0], accN[nt][1]), bn2);
            u64 n23 = add2_(pk2(accN[nt][2], accN[nt][3]), bn2);
            u64 e01v = fma2_(be2, P_SEVEN, pk2(accE[nt][0], accE[nt][1]));
            u64 e23v = fma2_(be2, P_SEVEN, pk2(accE[nt][2], accE[nt][3]));
            float a, b;
            upk2(a, b, n01); *(float2*)(c0 + swn) = make_float2(f2tff(a), f2tff(b));
            upk2(a, b, n23); *(float2*)(c1 + swn) = make_float2(f2tff(a), f2tff(b));
            upk2(a, b, e01v); *(float2*)(c0 + swe) = make_float2(f2tff(a), f2tff(b));
            upk2(a, b, e23v); *(float2*)(c1 + swe) = make_float2(f2tff(a), f2tff(b));
        }
    }
    __syncthreads();

    // ---- MMA comb1 (N=128) ----
    float acc1[8][4];
    #pragma unroll
    for (int i = 0; i < 8; i++) { acc1[i][0]=acc1[i][1]=acc1[i][2]=acc1[i][3]=0.f; }
    warp_gemm<8>(sm + S_A, sm + S_WC1, acc1, m0, nb1, lr, lc);
    __syncthreads();

    // ---- Stage 4: G2 = gelu(acc1 + comb_b1) (packed) -> A ----
    {
        float* g0 = sm + S_A + (m0 + lr) * 128;
        float* g1 = g0 + 8 * 128;
        const int sl = lr << 2;
        #pragma unroll
        for (int nt = 0; nt < 8; nt++) {
            int col = nb1 + nt * 8 + lc * 2;
            int sw  = col ^ sl;
            float2 bf = *(const float2*)(comb_b1 + col);
            u64 b2 = pk2(bf.x, bf.y);
            u64 t01 = add2_(pk2(acc1[nt][0], acc1[nt][1]), b2);
            u64 t23 = add2_(pk2(acc1[nt][2], acc1[nt][3]), b2);
            u64 r01 = gelu2(t01, gc);
            u64 r23 = gelu2(t23, gc);
            float a, b;
            upk2(a, b, r01); *(float2*)(g0 + sw) = make_float2(f2tff(a), f2tff(b));
            upk2(a, b, r23); *(float2*)(g1 + sw) = make_float2(f2tff(a), f2tff(b));
        }
    }
    __syncthreads();

    // ---- MMA comb2 + epilogue ----
    float acc2[4][4];
    #pragma unroll
    for (int i = 0; i < 4; i++) { acc2[i][0]=acc2[i][1]=acc2[i][2]=acc2[i][3]=0.f; }
    warp_gemm<4>(sm + S_A, sm + S_WC2, acc2, m0, nb, lr, lc);

    {
        float* orow0 = out + ((size_t)bb * NXV + i0 + m0 + lr) * 64;
        float* orow1 = orow0 + 8 * 64;
        #pragma unroll
        for (int nt = 0; nt < 4; nt++) {
            int colx = nb + nt * 8 + lc * 2;
            float2 b = *(const float2*)(comb_b2 + colx);
            *(float2*)(orow0 + colx) = make_float2(acc2[nt][0] + b.x, acc2[nt][1] + b.y);
            *(float2*)(orow1 + colx) = make_float2(acc2[nt][2] + b.x, acc2[nt][3] + b.y);
        }
    }
}

extern "C" void kernel_launch(void* const* d_in, const int* in_sizes, int n_in,
                              void* d_out, int out_size)
{
    const float* u0      = (const float*)d_in[0];
    const float* x       = (const float*)d_in[1];
    const float* node_w1 = (const float*)d_in[2];
    const float* node_b1 = (const float*)d_in[3];
    const float* node_w2 = (const float*)d_in[4];
    const float* node_b2 = (const float*)d_in[5];
    const float* edge_w1 = (const float*)d_in[6];
    const float* edge_b1 = (const float*)d_in[7];
    const float* edge_w2 = (const float*)d_in[8];
    const float* edge_b2 = (const float*)d_in[9];
    const float* comb_w1 = (const float*)d_in[10];
    const float* comb_b1 = (const float*)d_in[11];
    const float* comb_w2 = (const float*)d_in[12];
    const float* comb_b2 = (const float*)d_in[13];
    float* out = (float*)d_out;

    prep_kernel<<<48, 256>>>(node_w2, edge_w2, comb_w2, comb_w1);

    const size_t smem = SMEM_FLOATS * sizeof(float);
    cudaFuncSetAttribute(lifting_mma_kernel,
                         cudaFuncAttributeMaxDynamicSharedMemorySize, (int)smem);
    lifting_mma_kernel<<<NBLK, NT, smem>>>(u0, x,
                                           node_w1, node_b1, node_b2,
                                           edge_w1, edge_b1, edge_b2,
                                           comb_b1, comb_b2,
                                           out);
}

// round 10
// speedup vs baseline: 2.8794x; 1.0454x over previous
#include <cuda_runtime.h>
#include <cstdint>
#include <math.h>

// ---------------- problem constants ----------------
#define NXV 16384
#define BV  16
#define TP  128           // points per block
#define NT  512           // threads per block (16 warps)
#define NBLK (BV * (NXV / TP))   // 2048

// ---------------- swizzled A-tile addressing ----------------
__device__ __forceinline__ int SW(int row, int k) {
    return row * 128 + (k ^ ((row & 7) << 2));
}

// ---------------- smem layout (float offsets) ----------------
#define S_A   0                  // activation / C / G2 buffer 128 x 128
#define S_WN2 16384              // node_w2 fragment image  (8192 f)
#define S_WE2 24576              // edge_w2 fragment image  (8192 f)
#define S_WC2 32768              // comb_w2 fragment image  (8192 f)
#define S_WC1 40960              // comb_w1 fragment image  (16384 f)
#define S_U   57344              // u halo (134 -> 136)
#define S_X   (S_U + 136)
#define SMEM_FLOATS (S_X + 136)  // 57616 floats = 230464 B

#define WIMG_FLOATS 40960
__device__ float W_IMG[WIMG_FLOATS];

typedef unsigned long long u64;

// ---------------- packed f32x2 helpers (for stage3 epilogue) ----------------
__device__ __forceinline__ u64 pk2(float lo, float hi) {
    u64 r; asm("mov.b64 %0,{%1,%2};" : "=l"(r) : "f"(lo), "f"(hi)); return r;
}

// ---------------- gelu: A&S 7.1.28, one asm block, scalar-f32 interface ----------------
// gelu(t) = 0.5 t + ax*h ; ax = |t|/sqrt2 ; h = 0.7071*(1 - r^16), r = 1/poly(ax)
struct GConst { u64 CINV, ABSM, A6, A5, A4, A3, A2, A1, ONE, NCV, HALF; };
__device__ __forceinline__ GConst make_gc() {
    GConst g;
    g.CINV = 0x3F3504F33F3504F3ULL;   // 0.70710678 x2
    g.ABSM = 0x7FFFFFFF7FFFFFFFULL;
    g.A6   = pk2(0.0000430638f, 0.0000430638f);
    g.A5   = pk2(0.0002765672f, 0.0002765672f);
    g.A4   = pk2(0.0001520143f, 0.0001520143f);
    g.A3   = pk2(0.0092705272f, 0.0092705272f);
    g.A2   = pk2(0.0422820123f, 0.0422820123f);
    g.A1   = pk2(0.0705230784f, 0.0705230784f);
    g.ONE  = 0x3F8000003F800000ULL;
    g.NCV  = 0xBF3504F3BF3504F3ULL;   // -0.70710678 x2
    g.HALF = 0x3F0000003F000000ULL;
    return g;
}

// s += gelu(t) for a packed pair, scalar float interface
__device__ __forceinline__ void gelu2_acc2(float tlo, float thi,
                                           float& slo, float& shi, const GConst& g) {
    asm("{\n\t"
        ".reg .b64 t2,s2,ax,d,r;\n\t"
        ".reg .f32 dl,dh;\n\t"
        "mov.b64 t2,{%2,%3};\n\t"
        "mov.b64 s2,{%0,%1};\n\t"
        "mul.rn.f32x2 ax,t2,%4;\n\t"
        "and.b64 ax,ax,%5;\n\t"
        "fma.rn.f32x2 d,ax,%6,%7;\n\t"
        "fma.rn.f32x2 d,d,ax,%8;\n\t"
        "fma.rn.f32x2 d,d,ax,%9;\n\t"
        "fma.rn.f32x2 d,d,ax,%10;\n\t"
        "fma.rn.f32x2 d,d,ax,%11;\n\t"
        "fma.rn.f32x2 d,d,ax,%12;\n\t"
        "mov.b64 {dl,dh},d;\n\t"
        "rcp.approx.f32 dl,dl;\n\t"
        "rcp.approx.f32 dh,dh;\n\t"
        "mov.b64 r,{dl,dh};\n\t"
        "mul.rn.f32x2 r,r,r;\n\t"
        "mul.rn.f32x2 r,r,r;\n\t"
        "mul.rn.f32x2 r,r,r;\n\t"
        "mul.rn.f32x2 r,r,r;\n\t"
        "fma.rn.f32x2 r,r,%13,%4;\n\t"
        "fma.rn.f32x2 s2,t2,%14,s2;\n\t"
        "fma.rn.f32x2 s2,ax,r,s2;\n\t"
        "mov.b64 {%0,%1},s2;\n\t"
        "}"
        : "+f"(slo), "+f"(shi)
        : "f"(tlo), "f"(thi),
          "l"(g.CINV), "l"(g.ABSM), "l"(g.A6), "l"(g.A5), "l"(g.A4),
          "l"(g.A3), "l"(g.A2), "l"(g.A1), "l"(g.ONE), "l"(g.NCV), "l"(g.HALF));
}

// (olo,ohi) = gelu(t) for a packed pair
__device__ __forceinline__ void gelu2p(float tlo, float thi,
                                       float& olo, float& ohi, const GConst& g) {
    asm("{\n\t"
        ".reg .b64 t2,ax,d,r;\n\t"
        ".reg .f32 dl,dh;\n\t"
        "mov.b64 t2,{%2,%3};\n\t"
        "mul.rn.f32x2 ax,t2,%4;\n\t"
        "and.b64 ax,ax,%5;\n\t"
        "fma.rn.f32x2 d,ax,%6,%7;\n\t"
        "fma.rn.f32x2 d,d,ax,%8;\n\t"
        "fma.rn.f32x2 d,d,ax,%9;\n\t"
        "fma.rn.f32x2 d,d,ax,%10;\n\t"
        "fma.rn.f32x2 d,d,ax,%11;\n\t"
        "fma.rn.f32x2 d,d,ax,%12;\n\t"
        "mov.b64 {dl,dh},d;\n\t"
        "rcp.approx.f32 dl,dl;\n\t"
        "rcp.approx.f32 dh,dh;\n\t"
        "mov.b64 r,{dl,dh};\n\t"
        "mul.rn.f32x2 r,r,r;\n\t"
        "mul.rn.f32x2 r,r,r;\n\t"
        "mul.rn.f32x2 r,r,r;\n\t"
        "mul.rn.f32x2 r,r,r;\n\t"
        "fma.rn.f32x2 r,r,%13,%4;\n\t"
        "mul.rn.f32x2 d,ax,r;\n\t"
        "fma.rn.f32x2 d,t2,%14,d;\n\t"
        "mov.b64 {%0,%1},d;\n\t"
        "}"
        : "=f"(olo), "=f"(ohi)
        : "f"(tlo), "f"(thi),
          "l"(g.CINV), "l"(g.ABSM), "l"(g.A6), "l"(g.A5), "l"(g.A4),
          "l"(g.A3), "l"(g.A2), "l"(g.A1), "l"(g.ONE), "l"(g.NCV), "l"(g.HALF));
}

// ---------------- misc helpers ----------------
__device__ __forceinline__ uint32_t smem_u32(const void* p) {
    uint32_t a;
    asm("{ .reg .u64 t; cvta.to.shared.u64 t, %1; cvt.u32.u64 %0, t; }" : "=r"(a) : "l"(p));
    return a;
}
__device__ __forceinline__ uint32_t f2tf(float f) {
    uint32_t r; asm("cvt.rna.tf32.f32 %0, %1;" : "=r"(r) : "f"(f)); return r;
}
__device__ __forceinline__ float f2tff(float f) { return __uint_as_float(f2tf(f)); }

__device__ __forceinline__ void mma_tf32(float c[4],
                                         uint32_t a0, uint32_t a1, uint32_t a2, uint32_t a3,
                                         uint32_t b0, uint32_t b1) {
    asm volatile("mma.sync.aligned.m16n8k8.row.col.f32.tf32.tf32.f32 "
                 "{%0,%1,%2,%3}, {%4,%5,%6,%7}, {%8,%9}, {%0,%1,%2,%3};"
                 : "+f"(c[0]), "+f"(c[1]), "+f"(c[2]), "+f"(c[3])
                 : "r"(a0), "r"(a1), "r"(a2), "r"(a3), "r"(b0), "r"(b1));
}
#define CP_ASYNC16(dst, src) \
    asm volatile("cp.async.cg.shared.global [%0], [%1], 16;" :: "r"((uint32_t)(dst)), "l"(src) : "memory")
#define CP_COMMIT() asm volatile("cp.async.commit_group;" ::: "memory")
#define CP_WAIT0()  asm volatile("cp.async.wait_group 0;" ::: "memory")

// warp GEMM: D[m16 x NTILES*8] += A[m16 x 128] @ W^T, K=128, tf32.
// A: swizzled smem tile (as before). WF: fragment-pair image [n8][k8][lane]{b0,b1}
// -> B loads are single LDS.64 with immediate offsets, zero address math.
template <int NTILES>
__device__ __forceinline__ void warp_gemm(const float* __restrict__ A,
                                          const float2* __restrict__ WF,
                                          float acc[NTILES][4],
                                          int m0, int n8base, int lr, int lc, int lane) {
    const float* ar0 = A + (m0 + lr) * 128;
    const float* ar1 = ar0 + 8 * 128;
    const float2* wb = WF + (size_t)(n8base * 16) * 32 + lane;
    const int sl = lr << 2;
    #pragma unroll
    for (int k8 = 0; k8 < 16; k8++) {
        int i0 = (k8 * 8 + lc) ^ sl;
        int i4 = i0 ^ 4;
        uint32_t a0 = __float_as_uint(ar0[i0]);
        uint32_t a1 = __float_as_uint(ar1[i0]);
        uint32_t a2 = __float_as_uint(ar0[i4]);
        uint32_t a3 = __float_as_uint(ar1[i4]);
        #pragma unroll
        for (int nt = 0; nt < NTILES; nt++) {
            float2 b = wb[(nt * 16 + k8) * 32];
            mma_tf32(acc[nt], a0, a1, a2, a3,
                     __float_as_uint(b.x), __float_as_uint(b.y));
        }
    }
}

// ---------------- prep: weights -> tf32-rounded fragment-pair images ----------------
// orig layout [K, N]; fragment element: b0=(k=k8*8+lc, n=n8*8+lr), b1=same k+4
__global__ void prep_kernel(const float* __restrict__ wn2, const float* __restrict__ we2,
                            const float* __restrict__ wc2, const float* __restrict__ wc1) {
    int stride = gridDim.x * blockDim.x;
    int t0 = blockIdx.x * blockDim.x + threadIdx.x;
    for (int i = t0; i < 128 * 64; i += stride) {
        int k = i >> 6, n = i & 63;
        int idx = (((n >> 3) * 16 + (k >> 3)) * 32 + (n & 7) * 4 + (k & 3)) * 2 + ((k >> 2) & 1);
        W_IMG[0     + idx] = f2tff(wn2[i]);
        W_IMG[8192  + idx] = f2tff(we2[i]);
        W_IMG[16384 + idx] = f2tff(wc2[i]);
    }
    for (int i = t0; i < 128 * 128; i += stride) {
        int k = i >> 7, n = i & 127;
        int idx = (((n >> 3) * 16 + (k >> 3)) * 32 + (n & 7) * 4 + (k & 3)) * 2 + ((k >> 2) & 1);
        W_IMG[24576 + idx] = f2tff(wc1[i]);
    }
}

// ---------------- main fused kernel ----------------
__global__ void __launch_bounds__(NT, 1)
lifting_mma_kernel(const float* __restrict__ u0,      const float* __restrict__ x,
                   const float* __restrict__ node_w1, const float* __restrict__ node_b1,
                   const float* __restrict__ node_b2,
                   const float* __restrict__ edge_w1, const float* __restrict__ edge_b1,
                   const float* __restrict__ edge_b2,
                   const float* __restrict__ comb_b1, const float* __restrict__ comb_b2,
                   float* __restrict__ out)
{
    extern __shared__ float sm[];
    const uint32_t smem_base = smem_u32(sm);
    const int tid  = threadIdx.x;
    const int w    = tid >> 5;
    const int lane = tid & 31;
    const int lr   = lane >> 2, lc = lane & 3;
    const int blk  = blockIdx.x;
    const int bb   = blk / (NXV / TP);
    const int i0   = (blk % (NXV / TP)) * TP;
    const float* row_u = u0 + (size_t)bb * NXV;
    const float* row_x = x  + (size_t)bb * NXV;

    // ---- weights: contiguous async copy of the fragment image ----
    {
        const uint32_t wdst = smem_base + S_WN2 * 4;
        uint64_t wsrc = __cvta_generic_to_global((const void*)W_IMG);
        #pragma unroll 4
        for (int i = tid; i < WIMG_FLOATS / 4; i += NT)
            CP_ASYNC16(wdst + i * 16, (const void*)(wsrc + (uint64_t)i * 16));
        CP_COMMIT();
    }
    // ---- halo (clamped) ----
    for (int t = tid; t < TP + 6; t += NT) {
        int gi = i0 - 3 + t;
        gi = gi < 0 ? 0 : (gi > NXV - 1 ? NXV - 1 : gi);
        sm[S_U + t] = row_u[gi];
        sm[S_X + t] = row_x[gi];
    }
    __syncthreads();

    const GConst gc = make_gc();

    const int hh = tid & 127;       // hidden unit
    const int ph = tid >> 7;        // phase 0..3
    const int m0 = (w & 7) * 16;    // warp m-strip
    const int nh = w >> 3;          // warp n-half
    const int n8b  = nh * 4;        // N=64 GEMM fragment base (nb/8)
    const int n8b1 = nh * 8;        // N=128 GEMM fragment base
    const int nb   = nh * 32;
    const int nb1  = nh * 64;

    // ---- Stage 1: edge layer-1 (7-offset gelu sum), 2-pair unroll -> A ----
    {
        const float e0 = edge_w1[hh];
        const float e1 = edge_w1[128 + hh];
        const float e2 = edge_w1[256 + hh];
        const float eb = edge_b1[hh];
        const float e01 = e0 + e1;
        #pragma unroll 2
        for (int i = 0; i < 16; i++) {
            const int p0 = 2 * ph + 8 * i;      // pair (p0, p0+1)
            float zz[8];
            #pragma unroll
            for (int j = 0; j < 8; j += 2) {    // z_j = e1*u + e2*x at halo idx p0+j
                float2 uu = *(const float2*)(sm + S_U + p0 + j);
                float2 xx = *(const float2*)(sm + S_X + p0 + j);
                zz[j]     = fmaf(e1, uu.x, e2 * xx.x);
                zz[j + 1] = fmaf(e1, uu.y, e2 * xx.y);
            }
            float ba = fmaf(e01, sm[S_U + p0 + 3], eb) - zz[3];
            float bc = fmaf(e01, sm[S_U + p0 + 4], eb) - zz[4];
            float sAl = 0.f, sAh = 0.f, sBl = 0.f, sBh = 0.f;  // 2 chains
            #pragma unroll
            for (int o = 0; o < 7; o++) {
                float tlo = ba + zz[o];
                float thi = bc + zz[o + 1];
                if (o & 1) gelu2_acc2(tlo, thi, sBl, sBh, gc);
                else       gelu2_acc2(tlo, thi, sAl, sAh, gc);
            }
            sm[S_A + SW(p0, hh)]     = f2tff(sAl + sBl);
            sm[S_A + SW(p0 + 1, hh)] = f2tff(sAh + sBh);
        }
    }
    CP_WAIT0();
    __syncthreads();

    // ---- MMA edge ----
    float accE[4][4];
    #pragma unroll
    for (int i = 0; i < 4; i++) { accE[i][0]=accE[i][1]=accE[i][2]=accE[i][3]=0.f; }
    warp_gemm<4>(sm + S_A, (const float2*)(sm + S_WE2), accE, m0, n8b, lr, lc, lane);
    __syncthreads();

    // ---- Stage 2: node layer-1 + gelu -> A ----
    {
        const float a0 = node_w1[hh];
        const float a1 = node_w1[128 + hh];
        const float nbb = node_b1[hh];
        #pragma unroll 2
        for (int i = 0; i < 16; i++) {
            const int p0 = 2 * ph + 8 * i;
            float va = fmaf(a0, sm[S_U + p0 + 3], fmaf(a1, sm[S_X + p0 + 3], nbb));
            float vb = fmaf(a0, sm[S_U + p0 + 4], fmaf(a1, sm[S_X + p0 + 4], nbb));
            float glo, ghi;
            gelu2p(va, vb, glo, ghi, gc);
            sm[S_A + SW(p0, hh)]     = f2tff(glo);
            sm[S_A + SW(p0 + 1, hh)] = f2tff(ghi);
        }
    }
    __syncthreads();

    // ---- MMA node ----
    float accN[4][4];
    #pragma unroll
    for (int i = 0; i < 4; i++) { accN[i][0]=accN[i][1]=accN[i][2]=accN[i][3]=0.f; }
    warp_gemm<4>(sm + S_A, (const float2*)(sm + S_WN2), accN, m0, n8b, lr, lc, lane);
    __syncthreads();

    // ---- Stage 3: assemble C = [h_self + b | agg + 7b] -> A ----
    {
        float* c0 = sm + S_A + (m0 + lr) * 128;
        float* c1 = c0 + 8 * 128;
        const int sl = lr << 2;
        #pragma unroll
        for (int nt = 0; nt < 4; nt++) {
            int colx = nb + nt * 8 + lc * 2;
            int swn = colx ^ sl;
            int swe = (64 + colx) ^ sl;
            float2 bn = *(const float2*)(node_b2 + colx);
            float2 be = *(const float2*)(edge_b2 + colx);
            *(float2*)(c0 + swn) = make_float2(f2tff(accN[nt][0] + bn.x), f2tff(accN[nt][1] + bn.y));
            *(float2*)(c1 + swn) = make_float2(f2tff(accN[nt][2] + bn.x), f2tff(accN[nt][3] + bn.y));
            *(float2*)(c0 + swe) = make_float2(f2tff(fmaf(7.f, be.x, accE[nt][0])),
                                               f2tff(fmaf(7.f, be.y, accE[nt][1])));
            *(float2*)(c1 + swe) = make_float2(f2tff(fmaf(7.f, be.x, accE[nt][2])),
                                               f2tff(fmaf(7.f, be.y, accE[nt][3])));
        }
    }
    __syncthreads();

    // ---- MMA comb1 (N=128) ----
    float acc1[8][4];
    #pragma unroll
    for (int i = 0; i < 8; i++) { acc1[i][0]=acc1[i][1]=acc1[i][2]=acc1[i][3]=0.f; }
    warp_gemm<8>(sm + S_A, (const float2*)(sm + S_WC1), acc1, m0, n8b1, lr, lc, lane);
    __syncthreads();

    // ---- Stage 4: G2 = gelu(acc1 + comb_b1) -> A ----
    {
        float* g0 = sm + S_A + (m0 + lr) * 128;
        float* g1 = g0 + 8 * 128;
        const int sl = lr << 2;
        #pragma unroll
        for (int nt = 0; nt < 8; nt++) {
            int col = nb1 + nt * 8 + lc * 2;
            int sw  = col ^ sl;
            float2 bf = *(const float2*)(comb_b1 + col);
            float r0, r1, r2, r3;
            gelu2p(acc1[nt][0] + bf.x, acc1[nt][1] + bf.y, r0, r1, gc);
            gelu2p(acc1[nt][2] + bf.x, acc1[nt][3] + bf.y, r2, r3, gc);
            *(float2*)(g0 + sw) = make_float2(f2tff(r0), f2tff(r1));
            *(float2*)(g1 + sw) = make_float2(f2tff(r2), f2tff(r3));
        }
    }
    __syncthreads();

    // ---- MMA comb2 + epilogue ----
    float acc2[4][4];
    #pragma unroll
    for (int i = 0; i < 4; i++) { acc2[i][0]=acc2[i][1]=acc2[i][2]=acc2[i][3]=0.f; }
    warp_gemm<4>(sm + S_A, (const float2*)(sm + S_WC2), acc2, m0, n8b, lr, lc, lane);

    {
        float* orow0 = out + ((size_t)bb * NXV + i0 + m0 + lr) * 64;
        float* orow1 = orow0 + 8 * 64;
        #pragma unroll
        for (int nt = 0; nt < 4; nt++) {
            int colx = nb + nt * 8 + lc * 2;
            float2 b = *(const float2*)(comb_b2 + colx);
            *(float2*)(orow0 + colx) = make_float2(acc2[nt][0] + b.x, acc2[nt][1] + b.y);
            *(float2*)(orow1 + colx) = make_float2(acc2[nt][2] + b.x, acc2[nt][3] + b.y);
        }
    }
}

extern "C" void kernel_launch(void* const* d_in, const int* in_sizes, int n_in,
                              void* d_out, int out_size)
{
    const float* u0      = (const float*)d_in[0];
    const float* x       = (const float*)d_in[1];
    const float* node_w1 = (const float*)d_in[2];
    const float* node_b1 = (const float*)d_in[3];
    const float* node_w2 = (const float*)d_in[4];
    const float* node_b2 = (const float*)d_in[5];
    const float* edge_w1 = (const float*)d_in[6];
    const float* edge_b1 = (const float*)d_in[7];
    const float* edge_w2 = (const float*)d_in[8];
    const float* edge_b2 = (const float*)d_in[9];
    const float* comb_w1 = (const float*)d_in[10];
    const float* comb_b1 = (const float*)d_in[11];
    const float* comb_w2 = (const float*)d_in[12];
    const float* comb_b2 = (const float*)d_in[13];
    float* out = (float*)d_out;

    prep_kernel<<<48, 256>>>(node_w2, edge_w2, comb_w2, comb_w1);

    const size_t smem = SMEM_FLOATS * sizeof(float);
    cudaFuncSetAttribute(lifting_mma_kernel,
                         cudaFuncAttributeMaxDynamicSharedMemorySize, (int)smem);
    lifting_mma_kernel<<<NBLK, NT, smem>>>(u0, x,
                                           node_w1, node_b1, node_b2,
                                           edge_w1, edge_b1, edge_b2,
                                           comb_b1, comb_b2,
                                           out);
}